// round 2
// baseline (speedup 1.0000x reference)
#include <cuda_runtime.h>
#include <cstdint>

#define EMB 64
#define MAX_N 150000

// Scratch (allocation-free rule: __device__ globals)
__device__ float g_x[MAX_N * EMB];
__device__ float g_y[MAX_N * EMB];
__device__ float g_acc[MAX_N * EMB];

// init: x = acc = concat(user, item); y = 0
__global__ void k_init(const float4* __restrict__ ue, const float4* __restrict__ ie,
                       int nu4, int n4, float4* __restrict__ x,
                       float4* __restrict__ acc, float4* __restrict__ y) {
    int i = blockIdx.x * blockDim.x + threadIdx.x;
    if (i >= n4) return;
    float4 v = (i < nu4) ? ue[i] : ie[i - nu4];
    x[i] = v;
    acc[i] = v;
    y[i] = make_float4(0.f, 0.f, 0.f, 0.f);
}

// SpMM scatter: y[row[e]] += val[e] * x[col[e]], 16 threads per edge (one float4 each)
__global__ void k_scatter(const int* __restrict__ row, const int* __restrict__ col,
                          const float* __restrict__ val, const float* __restrict__ x,
                          float* __restrict__ y, int nnz) {
    long long tid = (long long)blockIdx.x * blockDim.x + threadIdx.x;
    int e = (int)(tid >> 4);
    if (e >= nnz) return;
    int lane = (int)(tid & 15);
    int r = __ldg(row + e);
    int c = __ldg(col + e);
    float v = __ldg(val + e);
    float4 xv = __ldg((const float4*)(x + (size_t)c * EMB) + lane);
    float* dst = y + (size_t)r * EMB + (size_t)lane * 4;
    asm volatile("red.global.add.v4.f32 [%0], {%1, %2, %3, %4};"
                 :: "l"(dst), "f"(v * xv.x), "f"(v * xv.y), "f"(v * xv.z), "f"(v * xv.w)
                 : "memory");
}

// acc += y; zero xold (which becomes the next scatter target after swap)
__global__ void k_post(float4* __restrict__ acc, const float4* __restrict__ y,
                       float4* __restrict__ xold, int n4) {
    int i = blockIdx.x * blockDim.x + threadIdx.x;
    if (i >= n4) return;
    float4 a = acc[i];
    float4 b = y[i];
    a.x += b.x; a.y += b.y; a.z += b.z; a.w += b.w;
    acc[i] = a;
    xold[i] = make_float4(0.f, 0.f, 0.f, 0.f);
}

// out = (acc + y_last) / 4
__global__ void k_final(const float4* __restrict__ acc, const float4* __restrict__ y,
                        float4* __restrict__ out, int n4) {
    int i = blockIdx.x * blockDim.x + threadIdx.x;
    if (i >= n4) return;
    float4 a = acc[i];
    float4 b = y[i];
    float4 o;
    o.x = (a.x + b.x) * 0.25f;
    o.y = (a.y + b.y) * 0.25f;
    o.z = (a.z + b.z) * 0.25f;
    o.w = (a.w + b.w) * 0.25f;
    out[i] = o;
}

extern "C" void kernel_launch(void* const* d_in, const int* in_sizes, int n_in,
                              void* d_out, int out_size) {
    const float* ue = (const float*)d_in[0];
    const float* ie = (const float*)d_in[1];
    const int*   er = (const int*)d_in[2];
    const int*   ec = (const int*)d_in[3];
    const float* ev = (const float*)d_in[4];

    int nu  = in_sizes[0] / EMB;
    int ni  = in_sizes[1] / EMB;
    int nnz = in_sizes[2];
    int n   = nu + ni;
    int n4  = n * (EMB / 4);      // float4 elements per buffer
    int nu4 = nu * (EMB / 4);

    float *x, *y, *acc;
    cudaGetSymbolAddress((void**)&x,   g_x);
    cudaGetSymbolAddress((void**)&y,   g_y);
    cudaGetSymbolAddress((void**)&acc, g_acc);

    const int TPB = 256;
    int ew_blocks = (n4 + TPB - 1) / TPB;

    k_init<<<ew_blocks, TPB>>>((const float4*)ue, (const float4*)ie, nu4, n4,
                               (float4*)x, (float4*)acc, (float4*)y);

    long long sc_threads = (long long)nnz * 16;
    int sc_blocks = (int)((sc_threads + TPB - 1) / TPB);

    // Layer 1
    k_scatter<<<sc_blocks, TPB>>>(er, ec, ev, x, y, nnz);
    k_post<<<ew_blocks, TPB>>>((float4*)acc, (const float4*)y, (float4*)x, n4);
    { float* t = x; x = y; y = t; }

    // Layer 2
    k_scatter<<<sc_blocks, TPB>>>(er, ec, ev, x, y, nnz);
    k_post<<<ew_blocks, TPB>>>((float4*)acc, (const float4*)y, (float4*)x, n4);
    { float* t = x; x = y; y = t; }

    // Layer 3 (fuse acc+y and /4 into the output write)
    k_scatter<<<sc_blocks, TPB>>>(er, ec, ev, x, y, nnz);
    k_final<<<ew_blocks, TPB>>>((const float4*)acc, (const float4*)y,
                                (float4*)d_out, n4);
}

// round 3
// speedup vs baseline: 2.0644x; 2.0644x over previous
#include <cuda_runtime.h>
#include <cstdint>

#define EMB 64
#define MAX_N 150016
#define MAX_NNZ 4000000
#define SCAN_B 512

// Scratch (__device__ globals per allocation-free rule)
__device__ float g_x[MAX_N * EMB];
__device__ float g_y[MAX_N * EMB];
__device__ float g_acc[MAX_N * EMB];
__device__ int   g_deg[MAX_N];
__device__ int   g_ptr[MAX_N];
__device__ int   g_cur[MAX_N];
__device__ int   g_blksum[1024];
__device__ int2  g_sedge[MAX_NNZ];   // packed (col, val-as-int)

// ---------------- CSR build ----------------

__global__ void k_zero_deg(int* __restrict__ deg, int n) {
    int i = blockIdx.x * blockDim.x + threadIdx.x;
    if (i < n) deg[i] = 0;
}

__global__ void k_hist(const int* __restrict__ row, int* __restrict__ deg, int nnz) {
    int i = blockIdx.x * blockDim.x + threadIdx.x;
    if (i < nnz) atomicAdd(&deg[row[i]], 1);
}

// per-block exclusive scan (SCAN_B elements per block), emit block totals
__global__ void k_scan1(const int* __restrict__ deg, int* __restrict__ ptr,
                        int* __restrict__ blksum, int n) {
    __shared__ int sh[SCAN_B];
    int i = blockIdx.x * SCAN_B + threadIdx.x;
    int v = (i < n) ? deg[i] : 0;
    sh[threadIdx.x] = v;
    __syncthreads();
    for (int off = 1; off < SCAN_B; off <<= 1) {
        int t = (threadIdx.x >= off) ? sh[threadIdx.x - off] : 0;
        __syncthreads();
        sh[threadIdx.x] += t;
        __syncthreads();
    }
    if (i < n) ptr[i] = sh[threadIdx.x] - v;            // exclusive
    if (threadIdx.x == SCAN_B - 1) blksum[blockIdx.x] = sh[SCAN_B - 1];
}

// single-block exclusive scan over block sums (nb <= SCAN_B)
__global__ void k_scan2(int* __restrict__ blksum, int nb) {
    __shared__ int sh[SCAN_B];
    int v = (threadIdx.x < nb) ? blksum[threadIdx.x] : 0;
    sh[threadIdx.x] = v;
    __syncthreads();
    for (int off = 1; off < SCAN_B; off <<= 1) {
        int t = (threadIdx.x >= off) ? sh[threadIdx.x - off] : 0;
        __syncthreads();
        sh[threadIdx.x] += t;
        __syncthreads();
    }
    if (threadIdx.x < nb) blksum[threadIdx.x] = sh[threadIdx.x] - v;
}

__global__ void k_scan3(int* __restrict__ ptr, const int* __restrict__ blksum,
                        int* __restrict__ cur, int n) {
    int i = blockIdx.x * SCAN_B + threadIdx.x;
    if (i < n) {
        int p = ptr[i] + blksum[blockIdx.x];
        ptr[i] = p;
        cur[i] = p;
    }
}

__global__ void k_fill(const int* __restrict__ row, const int* __restrict__ col,
                       const float* __restrict__ val, int* __restrict__ cur,
                       int2* __restrict__ sedge, int nnz) {
    int i = blockIdx.x * blockDim.x + threadIdx.x;
    if (i >= nnz) return;
    int r = row[i];
    int pos = atomicAdd(&cur[r], 1);
    sedge[pos] = make_int2(col[i], __float_as_int(val[i]));
}

// ---------------- init ----------------

__global__ void k_init(const float4* __restrict__ ue, const float4* __restrict__ ie,
                       int nu4, int n4, float4* __restrict__ x,
                       float4* __restrict__ acc) {
    int i = blockIdx.x * blockDim.x + threadIdx.x;
    if (i >= n4) return;
    float4 v = (i < nu4) ? ue[i] : ie[i - nu4];
    x[i] = v;
    acc[i] = v;
}

// ---------------- gather SpMM with fused epilogue ----------------
// 16 threads per row; each thread owns one float4 (4 emb dims).
// mode 0: y[r] = s; acc[r] += s
// mode 1: out[r] = (acc[r] + s) * 0.25
__global__ void k_spmm(const int* __restrict__ ptr, const int* __restrict__ deg,
                       const int2* __restrict__ sedge, const float4* __restrict__ x,
                       float4* __restrict__ y, float4* __restrict__ acc,
                       float4* __restrict__ out, int n, int mode) {
    int t = blockIdx.x * blockDim.x + threadIdx.x;
    int r = t >> 4;
    if (r >= n) return;
    int lane = t & 15;

    int start = __ldg(ptr + r);
    int d = __ldg(deg + r);

    float4 s0 = make_float4(0.f, 0.f, 0.f, 0.f);
    float4 s1 = make_float4(0.f, 0.f, 0.f, 0.f);

    int j = 0;
    for (; j + 4 <= d; j += 4) {
        int2 e0 = __ldg(sedge + start + j);
        int2 e1 = __ldg(sedge + start + j + 1);
        int2 e2 = __ldg(sedge + start + j + 2);
        int2 e3 = __ldg(sedge + start + j + 3);
        float4 x0 = __ldg(x + (size_t)e0.x * 16 + lane);
        float4 x1 = __ldg(x + (size_t)e1.x * 16 + lane);
        float4 x2 = __ldg(x + (size_t)e2.x * 16 + lane);
        float4 x3 = __ldg(x + (size_t)e3.x * 16 + lane);
        float v0 = __int_as_float(e0.y), v1 = __int_as_float(e1.y);
        float v2 = __int_as_float(e2.y), v3 = __int_as_float(e3.y);
        s0.x += v0 * x0.x; s0.y += v0 * x0.y; s0.z += v0 * x0.z; s0.w += v0 * x0.w;
        s1.x += v1 * x1.x; s1.y += v1 * x1.y; s1.z += v1 * x1.z; s1.w += v1 * x1.w;
        s0.x += v2 * x2.x; s0.y += v2 * x2.y; s0.z += v2 * x2.z; s0.w += v2 * x2.w;
        s1.x += v3 * x3.x; s1.y += v3 * x3.y; s1.z += v3 * x3.z; s1.w += v3 * x3.w;
    }
    for (; j < d; j++) {
        int2 e = __ldg(sedge + start + j);
        float4 xv = __ldg(x + (size_t)e.x * 16 + lane);
        float v = __int_as_float(e.y);
        s0.x += v * xv.x; s0.y += v * xv.y; s0.z += v * xv.z; s0.w += v * xv.w;
    }
    float4 s = make_float4(s0.x + s1.x, s0.y + s1.y, s0.z + s1.z, s0.w + s1.w);

    size_t idx = (size_t)r * 16 + lane;
    if (mode == 0) {
        y[idx] = s;
        float4 a = acc[idx];
        a.x += s.x; a.y += s.y; a.z += s.z; a.w += s.w;
        acc[idx] = a;
    } else {
        float4 a = acc[idx];
        float4 o;
        o.x = (a.x + s.x) * 0.25f;
        o.y = (a.y + s.y) * 0.25f;
        o.z = (a.z + s.z) * 0.25f;
        o.w = (a.w + s.w) * 0.25f;
        out[idx] = o;
    }
}

extern "C" void kernel_launch(void* const* d_in, const int* in_sizes, int n_in,
                              void* d_out, int out_size) {
    const float* ue = (const float*)d_in[0];
    const float* ie = (const float*)d_in[1];
    const int*   er = (const int*)d_in[2];
    const int*   ec = (const int*)d_in[3];
    const float* ev = (const float*)d_in[4];

    int nu  = in_sizes[0] / EMB;
    int ni  = in_sizes[1] / EMB;
    int nnz = in_sizes[2];
    int n   = nu + ni;
    int n4  = n * (EMB / 4);
    int nu4 = nu * (EMB / 4);

    float *x, *y, *acc;
    int *deg, *ptr, *cur, *blksum;
    int2 *sedge;
    cudaGetSymbolAddress((void**)&x,      g_x);
    cudaGetSymbolAddress((void**)&y,      g_y);
    cudaGetSymbolAddress((void**)&acc,    g_acc);
    cudaGetSymbolAddress((void**)&deg,    g_deg);
    cudaGetSymbolAddress((void**)&ptr,    g_ptr);
    cudaGetSymbolAddress((void**)&cur,    g_cur);
    cudaGetSymbolAddress((void**)&blksum, g_blksum);
    cudaGetSymbolAddress((void**)&sedge,  g_sedge);

    const int TPB = 256;
    int nb_scan = (n + SCAN_B - 1) / SCAN_B;

    // CSR build
    k_zero_deg<<<(n + TPB - 1) / TPB, TPB>>>(deg, n);
    k_hist<<<(nnz + TPB - 1) / TPB, TPB>>>(er, deg, nnz);
    k_scan1<<<nb_scan, SCAN_B>>>(deg, ptr, blksum, n);
    k_scan2<<<1, SCAN_B>>>(blksum, nb_scan);
    k_scan3<<<nb_scan, SCAN_B>>>(ptr, blksum, cur, n);
    k_fill<<<(nnz + TPB - 1) / TPB, TPB>>>(er, ec, ev, cur, sedge, nnz);

    // init x = acc = concat(user, item)
    k_init<<<(n4 + TPB - 1) / TPB, TPB>>>((const float4*)ue, (const float4*)ie,
                                          nu4, n4, (float4*)x, (float4*)acc);

    int sp_blocks = (n * 16 + TPB - 1) / TPB;

    // Layer 1: y = A*x ; acc += y
    k_spmm<<<sp_blocks, TPB>>>(ptr, deg, sedge, (const float4*)x,
                               (float4*)y, (float4*)acc, nullptr, n, 0);
    // Layer 2: x = A*y ; acc += x   (swap roles)
    k_spmm<<<sp_blocks, TPB>>>(ptr, deg, sedge, (const float4*)y,
                               (float4*)x, (float4*)acc, nullptr, n, 0);
    // Layer 3: out = (acc + A*x) / 4
    k_spmm<<<sp_blocks, TPB>>>(ptr, deg, sedge, (const float4*)x,
                               nullptr, (float4*)acc, (float4*)d_out, n, 1);
}

// round 4
// speedup vs baseline: 2.2259x; 1.0783x over previous
#include <cuda_runtime.h>
#include <cstdint>

#define EMB 64
#define MAX_N 150016
#define MAX_NNZ 4000000
#define SCAN_B 512

// Scratch (__device__ globals per allocation-free rule)
__device__ float g_x[MAX_N * EMB];
__device__ float g_y[MAX_N * EMB];
__device__ float g_acc[MAX_N * EMB];
__device__ int   g_deg[MAX_N];
__device__ int   g_ptr[MAX_N];
__device__ int   g_cur[MAX_N];
__device__ int   g_blksum[1024];
__device__ int2  g_sedge[MAX_NNZ];   // packed (col, val-as-int)

// ---------------- CSR build ----------------

__global__ void k_hist(const int* __restrict__ row, int* __restrict__ deg, int nnz) {
    int i = blockIdx.x * blockDim.x + threadIdx.x;
    if (i < nnz) atomicAdd(&deg[row[i]], 1);
}

__global__ void k_scan1(const int* __restrict__ deg, int* __restrict__ ptr,
                        int* __restrict__ blksum, int n) {
    __shared__ int sh[SCAN_B];
    int i = blockIdx.x * SCAN_B + threadIdx.x;
    int v = (i < n) ? deg[i] : 0;
    sh[threadIdx.x] = v;
    __syncthreads();
    for (int off = 1; off < SCAN_B; off <<= 1) {
        int t = (threadIdx.x >= off) ? sh[threadIdx.x - off] : 0;
        __syncthreads();
        sh[threadIdx.x] += t;
        __syncthreads();
    }
    if (i < n) ptr[i] = sh[threadIdx.x] - v;            // exclusive
    if (threadIdx.x == SCAN_B - 1) blksum[blockIdx.x] = sh[SCAN_B - 1];
}

__global__ void k_scan2(int* __restrict__ blksum, int nb) {
    __shared__ int sh[SCAN_B];
    int v = (threadIdx.x < nb) ? blksum[threadIdx.x] : 0;
    sh[threadIdx.x] = v;
    __syncthreads();
    for (int off = 1; off < SCAN_B; off <<= 1) {
        int t = (threadIdx.x >= off) ? sh[threadIdx.x - off] : 0;
        __syncthreads();
        sh[threadIdx.x] += t;
        __syncthreads();
    }
    if (threadIdx.x < nb) blksum[threadIdx.x] = sh[threadIdx.x] - v;
}

__global__ void k_scan3(int* __restrict__ ptr, const int* __restrict__ blksum,
                        int* __restrict__ cur, int n) {
    int i = blockIdx.x * SCAN_B + threadIdx.x;
    if (i < n) {
        int p = ptr[i] + blksum[blockIdx.x];
        ptr[i] = p;
        cur[i] = p;
    }
}

__global__ void k_fill(const int* __restrict__ row, const int* __restrict__ col,
                       const float* __restrict__ val, int* __restrict__ cur,
                       int2* __restrict__ sedge, int nnz) {
    int i = blockIdx.x * blockDim.x + threadIdx.x;
    if (i >= nnz) return;
    int r = __ldg(row + i);
    int pos = atomicAdd(&cur[r], 1);
    sedge[pos] = make_int2(__ldg(col + i), __float_as_int(__ldg(val + i)));
}

// ---------------- gather SpMM with fused epilogue ----------------
// 8 threads per row; each thread owns two float4s (lane and lane+8).
// MODE 0 (first layer): gather from ue/ie; y = s; acc = emb + s
// MODE 1 (middle):      gather from x;    y = s; acc += s
// MODE 2 (last):        gather from x;    out = (acc + s) * 0.25
template<int MODE>
__global__ void k_spmm(const int* __restrict__ ptr, const int* __restrict__ deg,
                       const int2* __restrict__ sedge,
                       const float4* __restrict__ ue, const float4* __restrict__ ie,
                       const float4* __restrict__ x,
                       float4* __restrict__ y, float4* __restrict__ acc,
                       float4* __restrict__ out, int n, int nu) {
    int t = blockIdx.x * blockDim.x + threadIdx.x;
    int r = t >> 3;
    if (r >= n) return;
    int lane = t & 7;

    int start = __ldg(ptr + r);
    int d = __ldg(deg + r);
    const int2* ep = sedge + start;

    float4 a0 = make_float4(0.f, 0.f, 0.f, 0.f);
    float4 b0 = make_float4(0.f, 0.f, 0.f, 0.f);
    float4 a1 = make_float4(0.f, 0.f, 0.f, 0.f);
    float4 b1 = make_float4(0.f, 0.f, 0.f, 0.f);

    int j = 0;
    for (; j + 2 <= d; j += 2) {
        int2 e0 = __ldg(ep + j);
        int2 e1 = __ldg(ep + j + 1);
        const float4* p0;
        const float4* p1;
        if (MODE == 0) {
            p0 = (e0.x < nu) ? ue + (size_t)e0.x * 16 : ie + (size_t)(e0.x - nu) * 16;
            p1 = (e1.x < nu) ? ue + (size_t)e1.x * 16 : ie + (size_t)(e1.x - nu) * 16;
        } else {
            p0 = x + (size_t)e0.x * 16;
            p1 = x + (size_t)e1.x * 16;
        }
        float4 xa0 = __ldcg(p0 + lane);
        float4 xb0 = __ldcg(p0 + 8 + lane);
        float4 xa1 = __ldcg(p1 + lane);
        float4 xb1 = __ldcg(p1 + 8 + lane);
        float v0 = __int_as_float(e0.y);
        float v1 = __int_as_float(e1.y);
        a0.x += v0 * xa0.x; a0.y += v0 * xa0.y; a0.z += v0 * xa0.z; a0.w += v0 * xa0.w;
        b0.x += v0 * xb0.x; b0.y += v0 * xb0.y; b0.z += v0 * xb0.z; b0.w += v0 * xb0.w;
        a1.x += v1 * xa1.x; a1.y += v1 * xa1.y; a1.z += v1 * xa1.z; a1.w += v1 * xa1.w;
        b1.x += v1 * xb1.x; b1.y += v1 * xb1.y; b1.z += v1 * xb1.z; b1.w += v1 * xb1.w;
    }
    if (j < d) {
        int2 e = __ldg(ep + j);
        const float4* p;
        if (MODE == 0) {
            p = (e.x < nu) ? ue + (size_t)e.x * 16 : ie + (size_t)(e.x - nu) * 16;
        } else {
            p = x + (size_t)e.x * 16;
        }
        float4 xa = __ldcg(p + lane);
        float4 xb = __ldcg(p + 8 + lane);
        float v = __int_as_float(e.y);
        a0.x += v * xa.x; a0.y += v * xa.y; a0.z += v * xa.z; a0.w += v * xa.w;
        b0.x += v * xb.x; b0.y += v * xb.y; b0.z += v * xb.z; b0.w += v * xb.w;
    }
    float4 sa = make_float4(a0.x + a1.x, a0.y + a1.y, a0.z + a1.z, a0.w + a1.w);
    float4 sb = make_float4(b0.x + b1.x, b0.y + b1.y, b0.z + b1.z, b0.w + b1.w);

    size_t ia = (size_t)r * 16 + lane;
    size_t ib = ia + 8;

    if (MODE == 0) {
        y[ia] = sa;
        y[ib] = sb;
        const float4* re = (r < nu) ? ue + (size_t)r * 16 : ie + (size_t)(r - nu) * 16;
        float4 e0 = __ldg(re + lane);
        float4 e1 = __ldg(re + 8 + lane);
        acc[ia] = make_float4(e0.x + sa.x, e0.y + sa.y, e0.z + sa.z, e0.w + sa.w);
        acc[ib] = make_float4(e1.x + sb.x, e1.y + sb.y, e1.z + sb.z, e1.w + sb.w);
    } else if (MODE == 1) {
        y[ia] = sa;
        y[ib] = sb;
        float4 q0 = acc[ia];
        float4 q1 = acc[ib];
        acc[ia] = make_float4(q0.x + sa.x, q0.y + sa.y, q0.z + sa.z, q0.w + sa.w);
        acc[ib] = make_float4(q1.x + sb.x, q1.y + sb.y, q1.z + sb.z, q1.w + sb.w);
    } else {
        float4 q0 = acc[ia];
        float4 q1 = acc[ib];
        out[ia] = make_float4((q0.x + sa.x) * 0.25f, (q0.y + sa.y) * 0.25f,
                              (q0.z + sa.z) * 0.25f, (q0.w + sa.w) * 0.25f);
        out[ib] = make_float4((q1.x + sb.x) * 0.25f, (q1.y + sb.y) * 0.25f,
                              (q1.z + sb.z) * 0.25f, (q1.w + sb.w) * 0.25f);
    }
}

extern "C" void kernel_launch(void* const* d_in, const int* in_sizes, int n_in,
                              void* d_out, int out_size) {
    const float* ue = (const float*)d_in[0];
    const float* ie = (const float*)d_in[1];
    const int*   er = (const int*)d_in[2];
    const int*   ec = (const int*)d_in[3];
    const float* ev = (const float*)d_in[4];

    int nu  = in_sizes[0] / EMB;
    int ni  = in_sizes[1] / EMB;
    int nnz = in_sizes[2];
    int n   = nu + ni;

    float *x, *y, *acc;
    int *deg, *ptr, *cur, *blksum;
    int2 *sedge;
    cudaGetSymbolAddress((void**)&x,      g_x);
    cudaGetSymbolAddress((void**)&y,      g_y);
    cudaGetSymbolAddress((void**)&acc,    g_acc);
    cudaGetSymbolAddress((void**)&deg,    g_deg);
    cudaGetSymbolAddress((void**)&ptr,    g_ptr);
    cudaGetSymbolAddress((void**)&cur,    g_cur);
    cudaGetSymbolAddress((void**)&blksum, g_blksum);
    cudaGetSymbolAddress((void**)&sedge,  g_sedge);

    const int TPB = 256;
    int nb_scan = (n + SCAN_B - 1) / SCAN_B;

    // CSR build
    cudaMemsetAsync(deg, 0, n * sizeof(int), 0);
    k_hist<<<(nnz + TPB - 1) / TPB, TPB>>>(er, deg, nnz);
    k_scan1<<<nb_scan, SCAN_B>>>(deg, ptr, blksum, n);
    k_scan2<<<1, SCAN_B>>>(blksum, nb_scan);
    k_scan3<<<nb_scan, SCAN_B>>>(ptr, blksum, cur, n);
    k_fill<<<(nnz + TPB - 1) / TPB, TPB>>>(er, ec, ev, cur, sedge, nnz);

    int sp_blocks = (n * 8 + TPB - 1) / TPB;

    // Layer 1: y = A*emb ; acc = emb + y   (gathers straight from inputs)
    k_spmm<0><<<sp_blocks, TPB>>>(ptr, deg, sedge, (const float4*)ue,
                                  (const float4*)ie, nullptr,
                                  (float4*)y, (float4*)acc, nullptr, n, nu);
    // Layer 2: x = A*y ; acc += x
    k_spmm<1><<<sp_blocks, TPB>>>(ptr, deg, sedge, nullptr, nullptr,
                                  (const float4*)y,
                                  (float4*)x, (float4*)acc, nullptr, n, nu);
    // Layer 3: out = (acc + A*x) / 4
    k_spmm<2><<<sp_blocks, TPB>>>(ptr, deg, sedge, nullptr, nullptr,
                                  (const float4*)x,
                                  nullptr, (float4*)acc, (float4*)d_out, n, nu);
}

// round 5
// speedup vs baseline: 2.3282x; 1.0459x over previous
#include <cuda_runtime.h>
#include <cuda_fp16.h>
#include <cstdint>

#define EMB 64
#define MAX_N 150016
#define MAX_NNZ 4000000
#define SCAN_B 512

// Scratch (__device__ globals per allocation-free rule)
__device__ __half g_xh[MAX_N * EMB];
__device__ __half g_yh[MAX_N * EMB];
__device__ float  g_acc[MAX_N * EMB];
__device__ int    g_deg[MAX_N];
__device__ int    g_ptr[MAX_N];
__device__ int    g_cur[MAX_N];
__device__ int    g_blksum[1024];
__device__ int2   g_sedge[MAX_NNZ];   // packed (col, val-as-int)

// ---------------- CSR build ----------------

__global__ void k_hist(const int* __restrict__ row, int* __restrict__ deg, int nnz) {
    int i = blockIdx.x * blockDim.x + threadIdx.x;
    if (i < nnz) atomicAdd(&deg[row[i]], 1);
}

__global__ void k_scan1(const int* __restrict__ deg, int* __restrict__ ptr,
                        int* __restrict__ blksum, int n) {
    __shared__ int sh[SCAN_B];
    int i = blockIdx.x * SCAN_B + threadIdx.x;
    int v = (i < n) ? deg[i] : 0;
    sh[threadIdx.x] = v;
    __syncthreads();
    for (int off = 1; off < SCAN_B; off <<= 1) {
        int t = (threadIdx.x >= off) ? sh[threadIdx.x - off] : 0;
        __syncthreads();
        sh[threadIdx.x] += t;
        __syncthreads();
    }
    if (i < n) ptr[i] = sh[threadIdx.x] - v;            // exclusive
    if (threadIdx.x == SCAN_B - 1) blksum[blockIdx.x] = sh[SCAN_B - 1];
}

__global__ void k_scan2(int* __restrict__ blksum, int nb) {
    __shared__ int sh[SCAN_B];
    int v = (threadIdx.x < nb) ? blksum[threadIdx.x] : 0;
    sh[threadIdx.x] = v;
    __syncthreads();
    for (int off = 1; off < SCAN_B; off <<= 1) {
        int t = (threadIdx.x >= off) ? sh[threadIdx.x - off] : 0;
        __syncthreads();
        sh[threadIdx.x] += t;
        __syncthreads();
    }
    if (threadIdx.x < nb) blksum[threadIdx.x] = sh[threadIdx.x] - v;
}

__global__ void k_scan3(int* __restrict__ ptr, const int* __restrict__ blksum,
                        int* __restrict__ cur, int n) {
    int i = blockIdx.x * SCAN_B + threadIdx.x;
    if (i < n) {
        int p = ptr[i] + blksum[blockIdx.x];
        ptr[i] = p;
        cur[i] = p;
    }
}

__global__ void k_fill(const int* __restrict__ row, const int* __restrict__ col,
                       const float* __restrict__ val, int* __restrict__ cur,
                       int2* __restrict__ sedge, int nnz) {
    int i = blockIdx.x * blockDim.x + threadIdx.x;
    if (i >= nnz) return;
    int r = __ldg(row + i);
    int pos = atomicAdd(&cur[r], 1);
    sedge[pos] = make_int2(__ldg(col + i), __float_as_int(__ldg(val + i)));
}

// ---------------- prologue: xh = half(concat(ue,ie)); acc = concat(ue,ie) ----
// one thread per 8 floats (= one uint4 of halves)
__global__ void k_conv(const float4* __restrict__ ue, const float4* __restrict__ ie,
                       int nu16, int n8, float4* __restrict__ acc,
                       uint4* __restrict__ xh) {
    int i = blockIdx.x * blockDim.x + threadIdx.x;
    if (i >= n8) return;
    int f4 = i * 2;
    float4 v0 = (f4     < nu16) ? __ldg(ue + f4)          : __ldg(ie + f4 - nu16);
    float4 v1 = (f4 + 1 < nu16) ? __ldg(ue + f4 + 1)      : __ldg(ie + f4 + 1 - nu16);
    acc[f4]     = v0;
    acc[f4 + 1] = v1;
    __half2 h0 = __floats2half2_rn(v0.x, v0.y);
    __half2 h1 = __floats2half2_rn(v0.z, v0.w);
    __half2 h2 = __floats2half2_rn(v1.x, v1.y);
    __half2 h3 = __floats2half2_rn(v1.z, v1.w);
    uint4 u;
    u.x = *reinterpret_cast<unsigned*>(&h0);
    u.y = *reinterpret_cast<unsigned*>(&h1);
    u.z = *reinterpret_cast<unsigned*>(&h2);
    u.w = *reinterpret_cast<unsigned*>(&h3);
    xh[i] = u;
}

// ---------------- fp16-gather SpMM with fused epilogue ----------------
// 8 threads per row; each lane owns 8 dims (one uint4 of halves).
// LAST=0: yh[r] = half(s); acc[r] += s
// LAST=1: out[r] = (acc[r] + s) * 0.25
__device__ __forceinline__ void fma8(float* s, float v, uint4 u) {
    __half2 h;
    *reinterpret_cast<unsigned*>(&h) = u.x; float2 f0 = __half22float2(h);
    *reinterpret_cast<unsigned*>(&h) = u.y; float2 f1 = __half22float2(h);
    *reinterpret_cast<unsigned*>(&h) = u.z; float2 f2 = __half22float2(h);
    *reinterpret_cast<unsigned*>(&h) = u.w; float2 f3 = __half22float2(h);
    s[0] += v * f0.x; s[1] += v * f0.y;
    s[2] += v * f1.x; s[3] += v * f1.y;
    s[4] += v * f2.x; s[5] += v * f2.y;
    s[6] += v * f3.x; s[7] += v * f3.y;
}

template<int LAST>
__global__ void k_spmm(const int* __restrict__ ptr, const int* __restrict__ deg,
                       const int2* __restrict__ sedge,
                       const __half* __restrict__ xh,
                       uint4* __restrict__ yh, float4* __restrict__ acc,
                       float4* __restrict__ out, int n) {
    int t = blockIdx.x * blockDim.x + threadIdx.x;
    int r = t >> 3;
    if (r >= n) return;
    int lane = t & 7;

    int start = __ldg(ptr + r);
    int d = __ldg(deg + r);
    const int2* ep = sedge + start;

    float s0[8] = {0,0,0,0,0,0,0,0};
    float s1[8] = {0,0,0,0,0,0,0,0};

    int j = 0;
    for (; j + 2 <= d; j += 2) {
        int2 e0 = __ldg(ep + j);
        int2 e1 = __ldg(ep + j + 1);
        const uint4* p0 = reinterpret_cast<const uint4*>(xh + (size_t)e0.x * EMB) + lane;
        const uint4* p1 = reinterpret_cast<const uint4*>(xh + (size_t)e1.x * EMB) + lane;
        uint4 u0 = __ldcg(p0);
        uint4 u1 = __ldcg(p1);
        fma8(s0, __int_as_float(e0.y), u0);
        fma8(s1, __int_as_float(e1.y), u1);
    }
    if (j < d) {
        int2 e = __ldg(ep + j);
        const uint4* p = reinterpret_cast<const uint4*>(xh + (size_t)e.x * EMB) + lane;
        uint4 u = __ldcg(p);
        fma8(s0, __int_as_float(e.y), u);
    }
    float s[8];
    #pragma unroll
    for (int k = 0; k < 8; k++) s[k] = s0[k] + s1[k];

    size_t f4 = (size_t)r * 16 + (size_t)lane * 2;   // float4 index into 64-dim row

    if (!LAST) {
        // yh[r] = half(s)
        __half2 h0 = __floats2half2_rn(s[0], s[1]);
        __half2 h1 = __floats2half2_rn(s[2], s[3]);
        __half2 h2 = __floats2half2_rn(s[4], s[5]);
        __half2 h3 = __floats2half2_rn(s[6], s[7]);
        uint4 u;
        u.x = *reinterpret_cast<unsigned*>(&h0);
        u.y = *reinterpret_cast<unsigned*>(&h1);
        u.z = *reinterpret_cast<unsigned*>(&h2);
        u.w = *reinterpret_cast<unsigned*>(&h3);
        yh[(size_t)r * 8 + lane] = u;
        // acc += s
        float4 q0 = acc[f4];
        float4 q1 = acc[f4 + 1];
        q0.x += s[0]; q0.y += s[1]; q0.z += s[2]; q0.w += s[3];
        q1.x += s[4]; q1.y += s[5]; q1.z += s[6]; q1.w += s[7];
        acc[f4]     = q0;
        acc[f4 + 1] = q1;
    } else {
        float4 q0 = acc[f4];
        float4 q1 = acc[f4 + 1];
        out[f4]     = make_float4((q0.x + s[0]) * 0.25f, (q0.y + s[1]) * 0.25f,
                                  (q0.z + s[2]) * 0.25f, (q0.w + s[3]) * 0.25f);
        out[f4 + 1] = make_float4((q1.x + s[4]) * 0.25f, (q1.y + s[5]) * 0.25f,
                                  (q1.z + s[6]) * 0.25f, (q1.w + s[7]) * 0.25f);
    }
}

extern "C" void kernel_launch(void* const* d_in, const int* in_sizes, int n_in,
                              void* d_out, int out_size) {
    const float* ue = (const float*)d_in[0];
    const float* ie = (const float*)d_in[1];
    const int*   er = (const int*)d_in[2];
    const int*   ec = (const int*)d_in[3];
    const float* ev = (const float*)d_in[4];

    int nu  = in_sizes[0] / EMB;
    int ni  = in_sizes[1] / EMB;
    int nnz = in_sizes[2];
    int n   = nu + ni;

    __half *xh, *yh;
    float *acc;
    int *deg, *ptr, *cur, *blksum;
    int2 *sedge;
    cudaGetSymbolAddress((void**)&xh,     g_xh);
    cudaGetSymbolAddress((void**)&yh,     g_yh);
    cudaGetSymbolAddress((void**)&acc,    g_acc);
    cudaGetSymbolAddress((void**)&deg,    g_deg);
    cudaGetSymbolAddress((void**)&ptr,    g_ptr);
    cudaGetSymbolAddress((void**)&cur,    g_cur);
    cudaGetSymbolAddress((void**)&blksum, g_blksum);
    cudaGetSymbolAddress((void**)&sedge,  g_sedge);

    const int TPB = 256;
    int nb_scan = (n + SCAN_B - 1) / SCAN_B;

    // CSR build
    cudaMemsetAsync(deg, 0, n * sizeof(int), 0);
    k_hist<<<(nnz + TPB - 1) / TPB, TPB>>>(er, deg, nnz);
    k_scan1<<<nb_scan, SCAN_B>>>(deg, ptr, blksum, n);
    k_scan2<<<1, SCAN_B>>>(blksum, nb_scan);
    k_scan3<<<nb_scan, SCAN_B>>>(ptr, blksum, cur, n);
    k_fill<<<(nnz + TPB - 1) / TPB, TPB>>>(er, ec, ev, cur, sedge, nnz);

    // prologue: xh = half(e); acc = e
    int n8 = n * 8;
    k_conv<<<(n8 + TPB - 1) / TPB, TPB>>>((const float4*)ue, (const float4*)ie,
                                          nu * 16, n8, (float4*)acc, (uint4*)xh);

    int sp_blocks = (n * 8 + TPB - 1) / TPB;

    // Layer 1: yh = half(A*xh); acc += A*xh
    k_spmm<0><<<sp_blocks, TPB>>>(ptr, deg, sedge, xh, (uint4*)yh,
                                  (float4*)acc, nullptr, n);
    // Layer 2: xh = half(A*yh); acc += A*yh
    k_spmm<0><<<sp_blocks, TPB>>>(ptr, deg, sedge, yh, (uint4*)xh,
                                  (float4*)acc, nullptr, n);
    // Layer 3: out = (acc + A*xh) / 4
    k_spmm<1><<<sp_blocks, TPB>>>(ptr, deg, sedge, xh, nullptr,
                                  (float4*)acc, (float4*)d_out, n);
}